// round 1
// baseline (speedup 1.0000x reference)
#include <cuda_runtime.h>
#include <math.h>

#define BN 2
#define TN 2048
#define HN 1024
#define DN 64
#define MN 16

#define QKV_ELEMS (BN*MN*TN*DN)

// ---- scratch (static device arrays; no allocation) ----
__device__ float  g_q[QKV_ELEMS];
__device__ float  g_k[QKV_ELEMS];
__device__ float  g_v[QKV_ELEMS];
__device__ double g_ent[BN*MN];
__device__ float  g_nmask[BN*MN];
__device__ float  g_comb[BN*TN*DN];
__device__ float  g_oproj[BN*DN*HN];

// ---- output layout (flattened tuple, f32) ----
#define OFF_SHA   (BN*TN*HN)                    // 4194304
#define OFF_LOGIT (OFF_SHA + BN*TN*MN*DN)       // 8388608
#define OFF_MASK  (OFF_LOGIT + BN*MN)           // 8388640
#define OFF_FBC   (OFF_MASK + BN*MN)            // 8388672

// ============================================================
// Generic 64x64 output-tile GEMM: C[64,64] = A[64,K] @ W[K,64]
// 256 threads, 4x4 micro-tile per thread, k-major smem (LDS.128,
// conflict-free inner loop).
// ============================================================
__device__ __forceinline__ void gemm64(const float* __restrict__ A, int lda,
                                       const float* __restrict__ W, int ldw,
                                       float* __restrict__ C, int ldc, int K)
{
    __shared__ float smem[16*68 + 16*64];
    float* sAt = smem;            // [k][row], stride 68
    float* sB  = smem + 16*68;    // [k][col], stride 64

    int tid = threadIdx.x;
    int r0 = (tid >> 4) << 2;
    int c0 = (tid & 15) << 2;
    int arow = tid >> 2;          // 0..63
    int ak   = (tid & 3) << 2;    // 0,4,8,12
    int wkr  = tid >> 4;          // 0..15
    int wn   = (tid & 15) << 2;   // 0..60

    float acc[4][4] = {};
    for (int k0 = 0; k0 < K; k0 += 16) {
        __syncthreads();
        float4 av = *(const float4*)(A + (size_t)arow*lda + k0 + ak);
        sAt[(ak+0)*68 + arow] = av.x;
        sAt[(ak+1)*68 + arow] = av.y;
        sAt[(ak+2)*68 + arow] = av.z;
        sAt[(ak+3)*68 + arow] = av.w;
        *(float4*)(sB + wkr*64 + wn) = *(const float4*)(W + (size_t)(k0+wkr)*ldw + wn);
        __syncthreads();
        #pragma unroll
        for (int kk = 0; kk < 16; kk++) {
            float4 a4 = *(const float4*)(sAt + kk*68 + r0);
            float4 b4 = *(const float4*)(sB  + kk*64 + c0);
            float a[4] = {a4.x, a4.y, a4.z, a4.w};
            float bb[4] = {b4.x, b4.y, b4.z, b4.w};
            #pragma unroll
            for (int i = 0; i < 4; i++)
                #pragma unroll
                for (int j = 0; j < 4; j++)
                    acc[i][j] = fmaf(a[i], bb[j], acc[i][j]);
        }
    }
    #pragma unroll
    for (int i = 0; i < 4; i++) {
        float4 o = make_float4(acc[i][0], acc[i][1], acc[i][2], acc[i][3]);
        *(float4*)(C + (size_t)(r0+i)*ldc + c0) = o;
    }
}

// ---- QKV projections: q/k/v[b,m,t,d] = hidden[b,t,:] @ w[m,:,d] ----
__global__ void proj_kernel(const float* __restrict__ hs,
                            const float* __restrict__ wq,
                            const float* __restrict__ wk,
                            const float* __restrict__ wv)
{
    int qt = blockIdx.x;              // T tile (32)
    int m  = blockIdx.y;              // expert (16)
    int b  = blockIdx.z / 3;
    int which = blockIdx.z % 3;
    const float* W = (which == 0 ? wq : which == 1 ? wk : wv) + (size_t)m*HN*DN;
    float* out = (which == 0 ? g_q : which == 1 ? g_k : g_v)
                 + ((size_t)(b*MN + m)*TN + (size_t)qt*64)*DN;
    const float* A = hs + (size_t)b*TN*HN + (size_t)qt*64*HN;
    gemm64(A, HN, W, DN, out, DN, HN);
}

// ---- init: zero entropy accumulators ----
__global__ void init_kernel() { g_ent[threadIdx.x] = 0.0; }

// ============================================================
// Flash attention per (b, m, q-tile of 64). Online softmax with
// fused entropy:  H_t = m + log(l) - t/l,  t = sum s*exp(s-m).
// Writes sha directly in [B,T,M,D] layout (the all_sha output).
// ============================================================
__global__ void attn_kernel(float* __restrict__ out_sha)
{
    extern __shared__ float sm[];
    float* sQt  = sm;                 // [64 k][64 row] stride 68
    float* sKt  = sQt + 64*68;
    float* sPt  = sKt + 64*68;        // P transposed: [c][r] stride 68
    float* sV   = sPt + 64*68;        // [c][d] stride 64
    float* sRed = sV  + 64*64;        // 16

    int tid = threadIdx.x;
    int qt = blockIdx.x, m = blockIdx.y, b = blockIdx.z;
    const float* Qg = g_q + ((size_t)(b*MN + m)*TN + (size_t)qt*64)*DN;
    const float* Kg = g_k + (size_t)(b*MN + m)*TN*DN;
    const float* Vg = g_v + (size_t)(b*MN + m)*TN*DN;

    int tr = tid >> 4, tc = tid & 15;
    int r0 = tr << 2, c0 = tc << 2;
    int lrow = tid >> 4;              // 0..15
    int ld4  = (tid & 15) << 2;       // 0..60

    // load Q transposed, pre-scaled by 1/sqrt(D)
    #pragma unroll
    for (int p = 0; p < 4; p++) {
        int row = lrow + p*16;
        float4 v = *(const float4*)(Qg + (size_t)row*DN + ld4);
        sQt[(ld4+0)*68 + row] = v.x * 0.125f;
        sQt[(ld4+1)*68 + row] = v.y * 0.125f;
        sQt[(ld4+2)*68 + row] = v.z * 0.125f;
        sQt[(ld4+3)*68 + row] = v.w * 0.125f;
    }

    float o[4][4] = {};
    float mrow[4], lrw[4], trw[4];
    #pragma unroll
    for (int i = 0; i < 4; i++) { mrow[i] = -INFINITY; lrw[i] = 0.f; trw[i] = 0.f; }

    for (int kt = 0; kt < TN/64; kt++) {
        __syncthreads();   // previous iteration fully done with sKt/sV/sPt
        #pragma unroll
        for (int p = 0; p < 4; p++) {
            int row = lrow + p*16;
            float4 kv = *(const float4*)(Kg + (size_t)(kt*64 + row)*DN + ld4);
            sKt[(ld4+0)*68 + row] = kv.x;
            sKt[(ld4+1)*68 + row] = kv.y;
            sKt[(ld4+2)*68 + row] = kv.z;
            sKt[(ld4+3)*68 + row] = kv.w;
            float4 vv = *(const float4*)(Vg + (size_t)(kt*64 + row)*DN + ld4);
            *(float4*)(sV + row*64 + ld4) = vv;
        }
        __syncthreads();

        // S = Q K^T (already scaled)
        float s[4][4] = {};
        #pragma unroll 8
        for (int kk = 0; kk < 64; kk++) {
            float4 a4 = *(const float4*)(sQt + kk*68 + r0);
            float4 b4 = *(const float4*)(sKt + kk*68 + c0);
            float a[4] = {a4.x, a4.y, a4.z, a4.w};
            float bb[4] = {b4.x, b4.y, b4.z, b4.w};
            #pragma unroll
            for (int i = 0; i < 4; i++)
                #pragma unroll
                for (int j = 0; j < 4; j++)
                    s[i][j] = fmaf(a[i], bb[j], s[i][j]);
        }

        // online softmax + entropy stats (rows owned by 16-lane groups)
        #pragma unroll
        for (int i = 0; i < 4; i++) {
            float mx = fmaxf(fmaxf(s[i][0], s[i][1]), fmaxf(s[i][2], s[i][3]));
            #pragma unroll
            for (int off = 8; off; off >>= 1)
                mx = fmaxf(mx, __shfl_xor_sync(0xffffffffu, mx, off));
            float mnew  = fmaxf(mrow[i], mx);
            float alpha = expf(mrow[i] - mnew);
            float ps = 0.f, ts = 0.f;
            #pragma unroll
            for (int j = 0; j < 4; j++) {
                float p = expf(s[i][j] - mnew);
                ps += p;
                ts += p * s[i][j];
                s[i][j] = p;
            }
            #pragma unroll
            for (int off = 8; off; off >>= 1) {
                ps += __shfl_xor_sync(0xffffffffu, ps, off);
                ts += __shfl_xor_sync(0xffffffffu, ts, off);
            }
            lrw[i] = lrw[i]*alpha + ps;
            trw[i] = trw[i]*alpha + ts;
            #pragma unroll
            for (int j = 0; j < 4; j++) o[i][j] *= alpha;
            mrow[i] = mnew;
        }

        // write P^T to smem
        #pragma unroll
        for (int j = 0; j < 4; j++) {
            float4 pv = make_float4(s[0][j], s[1][j], s[2][j], s[3][j]);
            *(float4*)(sPt + (c0+j)*68 + r0) = pv;
        }
        __syncthreads();

        // O += P V
        #pragma unroll 8
        for (int c = 0; c < 64; c++) {
            float4 a4 = *(const float4*)(sPt + c*68 + r0);
            float4 b4 = *(const float4*)(sV  + c*64 + c0);
            float a[4] = {a4.x, a4.y, a4.z, a4.w};
            float bb[4] = {b4.x, b4.y, b4.z, b4.w};
            #pragma unroll
            for (int i = 0; i < 4; i++)
                #pragma unroll
                for (int j = 0; j < 4; j++)
                    o[i][j] = fmaf(a[i], bb[j], o[i][j]);
        }
    }

    // epilogue: normalize + write sha in [B,T,M,D] layout
    #pragma unroll
    for (int i = 0; i < 4; i++) {
        float inv = 1.f / lrw[i];
        float4 ov = make_float4(o[i][0]*inv, o[i][1]*inv, o[i][2]*inv, o[i][3]*inv);
        size_t t = (size_t)qt*64 + r0 + i;
        *(float4*)(out_sha + (((size_t)b*TN + t)*MN + m)*DN + c0) = ov;
    }

    // entropy sum for this 64-row tile
    if (tc == 0) {
        float e = 0.f;
        #pragma unroll
        for (int i = 0; i < 4; i++)
            e += mrow[i] + logf(lrw[i]) - trw[i]/lrw[i];
        sRed[tr] = e;
    }
    __syncthreads();
    if (tid == 0) {
        float ssum = 0.f;
        #pragma unroll
        for (int k = 0; k < 16; k++) ssum += sRed[k];
        atomicAdd(&g_ent[b*MN + m], (double)ssum);
    }
}

// ---- gating: affinity -> normalize -> STE mask -> fallback top-2 ----
__global__ void gate_kernel(const float* __restrict__ gates, float* __restrict__ out)
{
    __shared__ int cnt;
    int tid = threadIdx.x;            // 0..31 : b = tid/16, m = tid%16
    if (tid == 0) cnt = 0;
    __syncthreads();
    int m = tid & 15;

    float aff = -(float)(g_ent[tid] * (1.0 / (double)TN));

    float s = aff;
    #pragma unroll
    for (int off = 8; off; off >>= 1) s += __shfl_xor_sync(0xffffffffu, s, off);
    float mu = s * (1.f/16.f);
    float d = aff - mu;
    float v = d*d;
    #pragma unroll
    for (int off = 8; off; off >>= 1) v += __shfl_xor_sync(0xffffffffu, v, off);
    float sd = sqrtf(v * (1.f/15.f));               // ddof=1
    float norm = d / (sd + 1e-9f);

    float g = gates[m];
    float logit = norm - 1.f/(1.f + expf(-g));
    float hard = (logit > 0.f) ? 1.f : 0.f;

    float nact = hard;
    #pragma unroll
    for (int off = 8; off; off >>= 1) nact += __shfl_xor_sync(0xffffffffu, nact, off);
    bool inactive = (nact == 0.f);

    // top-2 by normalized affinity (butterfly argmax, tie -> lower index)
    float v1 = norm; int i1 = m;
    #pragma unroll
    for (int off = 8; off; off >>= 1) {
        float ov = __shfl_xor_sync(0xffffffffu, v1, off);
        int   oi = __shfl_xor_sync(0xffffffffu, i1, off);
        if (ov > v1 || (ov == v1 && oi < i1)) { v1 = ov; i1 = oi; }
    }
    float v2 = (m == i1) ? -INFINITY : norm; int i2 = m;
    #pragma unroll
    for (int off = 8; off; off >>= 1) {
        float ov = __shfl_xor_sync(0xffffffffu, v2, off);
        int   oi = __shfl_xor_sync(0xffffffffu, i2, off);
        if (ov > v2 || (ov == v2 && oi < i2)) { v2 = ov; i2 = oi; }
    }

    float mask = hard;
    if (inactive && (m == i1 || m == i2)) mask = 1.f;

    float na = mask;
    #pragma unroll
    for (int off = 8; off; off >>= 1) na += __shfl_xor_sync(0xffffffffu, na, off);
    float nm = mask / fmaxf(na, 1.f);

    out[OFF_LOGIT + tid] = logit;
    out[OFF_MASK  + tid] = mask;
    g_nmask[tid] = nm;

    if (m == 0 && inactive) atomicAdd(&cnt, 1);
    __syncthreads();
    if (tid == 0) out[OFF_FBC] = (float)cnt;
}

// ---- combined_heads[b,t,d] = sum_m sha[b,t,m,d] * nmask[b,m] ----
__global__ void combine_kernel(const float* __restrict__ sha)
{
    __shared__ float snm[32];
    if (threadIdx.x < 32) snm[threadIdx.x] = g_nmask[threadIdx.x];
    __syncthreads();
    int idx = blockIdx.x*256 + threadIdx.x;     // B*T*D = 262144
    int d = idx & 63;
    int t = (idx >> 6) & (TN - 1);
    int b = idx >> 17;
    const float* base = sha + ((size_t)(b*TN + t)*MN)*DN + d;
    const float* w = snm + b*16;
    float acc = 0.f;
    #pragma unroll
    for (int mm = 0; mm < MN; mm++) acc = fmaf(base[mm*DN], w[mm], acc);
    g_comb[idx] = acc;
}

// ---- dynamic_o_proj[b,d,h] = sum_m o_weights[m,d,h] * nmask[b,m] ----
__global__ void oproj_kernel(const float* __restrict__ ow)
{
    __shared__ float snm[32];
    if (threadIdx.x < 32) snm[threadIdx.x] = g_nmask[threadIdx.x];
    __syncthreads();
    int idx = blockIdx.x*256 + threadIdx.x;     // B*D*H = 131072
    int h  = idx & (HN - 1);
    int dd = (idx >> 10) & 63;
    int b  = idx >> 16;
    float acc = 0.f;
    #pragma unroll
    for (int mm = 0; mm < MN; mm++)
        acc = fmaf(ow[((size_t)mm*DN + dd)*HN + h], snm[b*16 + mm], acc);
    g_oproj[idx] = acc;
}

// ---- final[b,t,h] = combined[b] @ oproj[b] ----
__global__ void final_kernel(float* __restrict__ out)
{
    int ht = blockIdx.x, qt = blockIdx.y, b = blockIdx.z;
    gemm64(g_comb  + (size_t)b*TN*DN + (size_t)qt*64*DN, DN,
           g_oproj + (size_t)b*DN*HN + ht*64,            HN,
           out     + (size_t)b*TN*HN + (size_t)qt*64*HN + ht*64, HN, DN);
}

extern "C" void kernel_launch(void* const* d_in, const int* in_sizes, int n_in,
                              void* d_out, int out_size)
{
    const float* hs    = (const float*)d_in[0];
    const float* wq    = (const float*)d_in[1];
    const float* wk    = (const float*)d_in[2];
    const float* wv    = (const float*)d_in[3];
    const float* ow    = (const float*)d_in[4];
    const float* gates = (const float*)d_in[5];
    float* out = (float*)d_out;

    const int attn_smem = (3*64*68 + 64*64 + 16) * 4;   // 68672 B
    cudaFuncSetAttribute(attn_kernel, cudaFuncAttributeMaxDynamicSharedMemorySize, attn_smem);

    init_kernel<<<1, 32>>>();
    proj_kernel<<<dim3(32, 16, 6), 256>>>(hs, wq, wk, wv);
    attn_kernel<<<dim3(32, 16, 2), 256, attn_smem>>>(out + OFF_SHA);
    gate_kernel<<<1, 32>>>(gates, out);
    combine_kernel<<<1024, 256>>>(out + OFF_SHA);
    oproj_kernel<<<512, 256>>>(ow);
    final_kernel<<<dim3(16, 32, 2), 256>>>(out);
}

// round 2
// speedup vs baseline: 1.0297x; 1.0297x over previous
#include <cuda_runtime.h>
#include <math.h>

#define BN 2
#define TN 2048
#define HN 1024
#define DN 64
#define MN 16

#define QKV_ELEMS (BN*MN*TN*DN)

typedef unsigned long long u64;

// ---- packed f32x2 helpers (Blackwell 2x-rate fp32 path) ----
__device__ __forceinline__ u64 pk2(float lo, float hi) {
    u64 r; asm("mov.b64 %0, {%1,%2};" : "=l"(r) : "f"(lo), "f"(hi)); return r;
}
__device__ __forceinline__ void upk2(float& lo, float& hi, u64 v) {
    asm("mov.b64 {%0,%1}, %2;" : "=f"(lo), "=f"(hi) : "l"(v));
}
__device__ __forceinline__ void ffma2(u64& d, u64 a, u64 b) {
    asm("fma.rn.f32x2 %0, %1, %2, %0;" : "+l"(d) : "l"(a), "l"(b));
}
__device__ __forceinline__ void fmul2(u64& d, u64 a) {
    asm("mul.rn.f32x2 %0, %0, %1;" : "+l"(d) : "l"(a));
}

// ---- scratch (static device arrays; no allocation) ----
__device__ float  g_q[QKV_ELEMS];
__device__ float  g_k[QKV_ELEMS];
__device__ float  g_v[QKV_ELEMS];
__device__ double g_ent[BN*MN];
__device__ float  g_nmask[BN*MN];
__device__ float  g_comb[BN*TN*DN];
__device__ float  g_oproj[BN*DN*HN];

// ---- output layout (flattened tuple, f32) ----
#define OFF_SHA   (BN*TN*HN)                    // 4194304
#define OFF_LOGIT (OFF_SHA + BN*TN*MN*DN)       // 8388608
#define OFF_MASK  (OFF_LOGIT + BN*MN)           // 8388640
#define OFF_FBC   (OFF_MASK + BN*MN)            // 8388672

// ============================================================
// Generic 64x64 output-tile GEMM: C[64,64] = A[64,K] @ W[K,64]
// 256 threads, 4x4 micro-tile per thread, packed f32x2 FMAs.
// ============================================================
__device__ __forceinline__ void gemm64(const float* __restrict__ A, int lda,
                                       const float* __restrict__ W, int ldw,
                                       float* __restrict__ C, int ldc, int K)
{
    __shared__ float smem[16*68 + 16*64];
    float* sAt = smem;            // [k][row], stride 68
    float* sB  = smem + 16*68;    // [k][col], stride 64

    int tid = threadIdx.x;
    int r0 = (tid >> 4) << 2;
    int c0 = (tid & 15) << 2;
    int arow = tid >> 2;          // 0..63
    int ak   = (tid & 3) << 2;    // 0,4,8,12
    int wkr  = tid >> 4;          // 0..15
    int wn   = (tid & 15) << 2;   // 0..60

    u64 acc2[4][2] = {};
    for (int k0 = 0; k0 < K; k0 += 16) {
        __syncthreads();
        float4 av = *(const float4*)(A + (size_t)arow*lda + k0 + ak);
        sAt[(ak+0)*68 + arow] = av.x;
        sAt[(ak+1)*68 + arow] = av.y;
        sAt[(ak+2)*68 + arow] = av.z;
        sAt[(ak+3)*68 + arow] = av.w;
        *(float4*)(sB + wkr*64 + wn) = *(const float4*)(W + (size_t)(k0+wkr)*ldw + wn);
        __syncthreads();
        #pragma unroll
        for (int kk = 0; kk < 16; kk++) {
            float4 a4 = *(const float4*)(sAt + kk*68 + r0);
            ulonglong2 bu = *(const ulonglong2*)(sB + kk*64 + c0);
            u64 a0 = pk2(a4.x, a4.x), a1 = pk2(a4.y, a4.y);
            u64 a2 = pk2(a4.z, a4.z), a3 = pk2(a4.w, a4.w);
            ffma2(acc2[0][0], a0, bu.x); ffma2(acc2[0][1], a0, bu.y);
            ffma2(acc2[1][0], a1, bu.x); ffma2(acc2[1][1], a1, bu.y);
            ffma2(acc2[2][0], a2, bu.x); ffma2(acc2[2][1], a2, bu.y);
            ffma2(acc2[3][0], a3, bu.x); ffma2(acc2[3][1], a3, bu.y);
        }
    }
    #pragma unroll
    for (int i = 0; i < 4; i++) {
        float4 o;
        upk2(o.x, o.y, acc2[i][0]);
        upk2(o.z, o.w, acc2[i][1]);
        *(float4*)(C + (size_t)(r0+i)*ldc + c0) = o;
    }
}

// ---- QKV projections: q/k/v[b,m,t,d] = hidden[b,t,:] @ w[m,:,d] ----
__global__ void proj_kernel(const float* __restrict__ hs,
                            const float* __restrict__ wq,
                            const float* __restrict__ wk,
                            const float* __restrict__ wv)
{
    int qt = blockIdx.x;              // T tile (32)
    int m  = blockIdx.y;              // expert (16)
    int b  = blockIdx.z / 3;
    int which = blockIdx.z % 3;
    const float* W = (which == 0 ? wq : which == 1 ? wk : wv) + (size_t)m*HN*DN;
    float* out = (which == 0 ? g_q : which == 1 ? g_k : g_v)
                 + ((size_t)(b*MN + m)*TN + (size_t)qt*64)*DN;
    const float* A = hs + (size_t)b*TN*HN + (size_t)qt*64*HN;
    gemm64(A, HN, W, DN, out, DN, HN);
}

// ---- init: zero entropy accumulators ----
__global__ void init_kernel() { g_ent[threadIdx.x] = 0.0; }

// ============================================================
// Flash attention per (b, m, q-tile of 64). Online softmax with
// fused entropy:  H_t = m + log(l) - t/l,  t = sum s*exp(s-m).
// Packed f32x2 FMAs in both GEMM loops.
// ============================================================
__global__ void attn_kernel(float* __restrict__ out_sha)
{
    extern __shared__ float sm[];
    float* sQt  = sm;                 // [64 k][64 row] stride 68
    float* sKt  = sQt + 64*68;
    float* sPt  = sKt + 64*68;        // P transposed: [c][r] stride 68
    float* sV   = sPt + 64*68;        // [c][d] stride 64
    float* sRed = sV  + 64*64;        // 16

    int tid = threadIdx.x;
    int qt = blockIdx.x, m = blockIdx.y, b = blockIdx.z;
    const float* Qg = g_q + ((size_t)(b*MN + m)*TN + (size_t)qt*64)*DN;
    const float* Kg = g_k + (size_t)(b*MN + m)*TN*DN;
    const float* Vg = g_v + (size_t)(b*MN + m)*TN*DN;

    int tr = tid >> 4, tc = tid & 15;
    int r0 = tr << 2, c0 = tc << 2;
    int lrow = tid >> 4;              // 0..15
    int ld4  = (tid & 15) << 2;       // 0..60

    // load Q transposed, pre-scaled by 1/sqrt(D)
    #pragma unroll
    for (int p = 0; p < 4; p++) {
        int row = lrow + p*16;
        float4 v = *(const float4*)(Qg + (size_t)row*DN + ld4);
        sQt[(ld4+0)*68 + row] = v.x * 0.125f;
        sQt[(ld4+1)*68 + row] = v.y * 0.125f;
        sQt[(ld4+2)*68 + row] = v.z * 0.125f;
        sQt[(ld4+3)*68 + row] = v.w * 0.125f;
    }

    u64 o2[4][2] = {};
    float mrow[4], lrw[4], trw[4];
    #pragma unroll
    for (int i = 0; i < 4; i++) { mrow[i] = -INFINITY; lrw[i] = 0.f; trw[i] = 0.f; }

    for (int kt = 0; kt < TN/64; kt++) {
        __syncthreads();   // previous iteration fully done with sKt/sV/sPt
        #pragma unroll
        for (int p = 0; p < 4; p++) {
            int row = lrow + p*16;
            float4 kv = *(const float4*)(Kg + (size_t)(kt*64 + row)*DN + ld4);
            sKt[(ld4+0)*68 + row] = kv.x;
            sKt[(ld4+1)*68 + row] = kv.y;
            sKt[(ld4+2)*68 + row] = kv.z;
            sKt[(ld4+3)*68 + row] = kv.w;
            float4 vv = *(const float4*)(Vg + (size_t)(kt*64 + row)*DN + ld4);
            *(float4*)(sV + row*64 + ld4) = vv;
        }
        __syncthreads();

        // S = Q K^T (already scaled) — packed f32x2
        u64 s2[4][2] = {};
        #pragma unroll 8
        for (int kk = 0; kk < 64; kk++) {
            float4 a4 = *(const float4*)(sQt + kk*68 + r0);
            ulonglong2 bu = *(const ulonglong2*)(sKt + kk*68 + c0);
            u64 a0 = pk2(a4.x, a4.x), a1 = pk2(a4.y, a4.y);
            u64 a2 = pk2(a4.z, a4.z), a3 = pk2(a4.w, a4.w);
            ffma2(s2[0][0], a0, bu.x); ffma2(s2[0][1], a0, bu.y);
            ffma2(s2[1][0], a1, bu.x); ffma2(s2[1][1], a1, bu.y);
            ffma2(s2[2][0], a2, bu.x); ffma2(s2[2][1], a2, bu.y);
            ffma2(s2[3][0], a3, bu.x); ffma2(s2[3][1], a3, bu.y);
        }
        float s[4][4];
        #pragma unroll
        for (int i = 0; i < 4; i++) {
            upk2(s[i][0], s[i][1], s2[i][0]);
            upk2(s[i][2], s[i][3], s2[i][1]);
        }

        // online softmax + entropy stats (rows owned by 16-lane groups)
        #pragma unroll
        for (int i = 0; i < 4; i++) {
            float mx = fmaxf(fmaxf(s[i][0], s[i][1]), fmaxf(s[i][2], s[i][3]));
            #pragma unroll
            for (int off = 8; off; off >>= 1)
                mx = fmaxf(mx, __shfl_xor_sync(0xffffffffu, mx, off));
            float mnew  = fmaxf(mrow[i], mx);
            float alpha = __expf(mrow[i] - mnew);
            float ps = 0.f, ts = 0.f;
            #pragma unroll
            for (int j = 0; j < 4; j++) {
                float p = __expf(s[i][j] - mnew);
                ps += p;
                ts += p * s[i][j];
                s[i][j] = p;
            }
            #pragma unroll
            for (int off = 8; off; off >>= 1) {
                ps += __shfl_xor_sync(0xffffffffu, ps, off);
                ts += __shfl_xor_sync(0xffffffffu, ts, off);
            }
            lrw[i] = lrw[i]*alpha + ps;
            trw[i] = trw[i]*alpha + ts;
            u64 al2 = pk2(alpha, alpha);
            fmul2(o2[i][0], al2);
            fmul2(o2[i][1], al2);
            mrow[i] = mnew;
        }

        // write P^T to smem
        #pragma unroll
        for (int j = 0; j < 4; j++) {
            float4 pv = make_float4(s[0][j], s[1][j], s[2][j], s[3][j]);
            *(float4*)(sPt + (c0+j)*68 + r0) = pv;
        }
        __syncthreads();

        // O += P V — packed f32x2
        #pragma unroll 8
        for (int c = 0; c < 64; c++) {
            float4 a4 = *(const float4*)(sPt + c*68 + r0);
            ulonglong2 bu = *(const ulonglong2*)(sV + c*64 + c0);
            u64 a0 = pk2(a4.x, a4.x), a1 = pk2(a4.y, a4.y);
            u64 a2 = pk2(a4.z, a4.z), a3 = pk2(a4.w, a4.w);
            ffma2(o2[0][0], a0, bu.x); ffma2(o2[0][1], a0, bu.y);
            ffma2(o2[1][0], a1, bu.x); ffma2(o2[1][1], a1, bu.y);
            ffma2(o2[2][0], a2, bu.x); ffma2(o2[2][1], a2, bu.y);
            ffma2(o2[3][0], a3, bu.x); ffma2(o2[3][1], a3, bu.y);
        }
    }

    // epilogue: normalize + write sha in [B,T,M,D] layout
    #pragma unroll
    for (int i = 0; i < 4; i++) {
        float inv = 1.f / lrw[i];
        float4 ov;
        upk2(ov.x, ov.y, o2[i][0]);
        upk2(ov.z, ov.w, o2[i][1]);
        ov.x *= inv; ov.y *= inv; ov.z *= inv; ov.w *= inv;
        size_t t = (size_t)qt*64 + r0 + i;
        *(float4*)(out_sha + (((size_t)b*TN + t)*MN + m)*DN + c0) = ov;
    }

    // entropy sum for this 64-row tile
    if (tc == 0) {
        float e = 0.f;
        #pragma unroll
        for (int i = 0; i < 4; i++)
            e += mrow[i] + logf(lrw[i]) - trw[i]/lrw[i];
        sRed[tr] = e;
    }
    __syncthreads();
    if (tid == 0) {
        float ssum = 0.f;
        #pragma unroll
        for (int k = 0; k < 16; k++) ssum += sRed[k];
        atomicAdd(&g_ent[b*MN + m], (double)ssum);
    }
}

// ---- gating: affinity -> normalize -> STE mask -> fallback top-2 ----
__global__ void gate_kernel(const float* __restrict__ gates, float* __restrict__ out)
{
    __shared__ int cnt;
    int tid = threadIdx.x;            // 0..31 : b = tid/16, m = tid%16
    if (tid == 0) cnt = 0;
    __syncthreads();
    int m = tid & 15;

    float aff = -(float)(g_ent[tid] * (1.0 / (double)TN));

    float s = aff;
    #pragma unroll
    for (int off = 8; off; off >>= 1) s += __shfl_xor_sync(0xffffffffu, s, off);
    float mu = s * (1.f/16.f);
    float d = aff - mu;
    float v = d*d;
    #pragma unroll
    for (int off = 8; off; off >>= 1) v += __shfl_xor_sync(0xffffffffu, v, off);
    float sd = sqrtf(v * (1.f/15.f));               // ddof=1
    float norm = d / (sd + 1e-9f);

    float g = gates[m];
    float logit = norm - 1.f/(1.f + expf(-g));
    float hard = (logit > 0.f) ? 1.f : 0.f;

    float nact = hard;
    #pragma unroll
    for (int off = 8; off; off >>= 1) nact += __shfl_xor_sync(0xffffffffu, nact, off);
    bool inactive = (nact == 0.f);

    // top-2 by normalized affinity (butterfly argmax, tie -> lower index)
    float v1 = norm; int i1 = m;
    #pragma unroll
    for (int off = 8; off; off >>= 1) {
        float ov = __shfl_xor_sync(0xffffffffu, v1, off);
        int   oi = __shfl_xor_sync(0xffffffffu, i1, off);
        if (ov > v1 || (ov == v1 && oi < i1)) { v1 = ov; i1 = oi; }
    }
    float v2 = (m == i1) ? -INFINITY : norm; int i2 = m;
    #pragma unroll
    for (int off = 8; off; off >>= 1) {
        float ov = __shfl_xor_sync(0xffffffffu, v2, off);
        int   oi = __shfl_xor_sync(0xffffffffu, i2, off);
        if (ov > v2 || (ov == v2 && oi < i2)) { v2 = ov; i2 = oi; }
    }

    float mask = hard;
    if (inactive && (m == i1 || m == i2)) mask = 1.f;

    float na = mask;
    #pragma unroll
    for (int off = 8; off; off >>= 1) na += __shfl_xor_sync(0xffffffffu, na, off);
    float nm = mask / fmaxf(na, 1.f);

    out[OFF_LOGIT + tid] = logit;
    out[OFF_MASK  + tid] = mask;
    g_nmask[tid] = nm;

    if (m == 0 && inactive) atomicAdd(&cnt, 1);
    __syncthreads();
    if (tid == 0) out[OFF_FBC] = (float)cnt;
}

// ---- combined_heads[b,t,d] = sum_m sha[b,t,m,d] * nmask[b,m] ----
__global__ void combine_kernel(const float* __restrict__ sha)
{
    __shared__ float snm[32];
    if (threadIdx.x < 32) snm[threadIdx.x] = g_nmask[threadIdx.x];
    __syncthreads();
    int idx4 = blockIdx.x*256 + threadIdx.x;    // B*T*D/4 = 65536
    int d4 = (idx4 & 15) << 2;
    int t  = (idx4 >> 4) & (TN - 1);
    int b  = idx4 >> 15;
    const float* base = sha + ((size_t)(b*TN + t)*MN)*DN + d4;
    const float* w = snm + b*16;
    float4 acc = make_float4(0.f, 0.f, 0.f, 0.f);
    #pragma unroll
    for (int mm = 0; mm < MN; mm++) {
        float4 v = *(const float4*)(base + mm*DN);
        float wm = w[mm];
        acc.x = fmaf(v.x, wm, acc.x);
        acc.y = fmaf(v.y, wm, acc.y);
        acc.z = fmaf(v.z, wm, acc.z);
        acc.w = fmaf(v.w, wm, acc.w);
    }
    *(float4*)(g_comb + (size_t)idx4*4) = acc;
}

// ---- dynamic_o_proj[b,d,h] = sum_m o_weights[m,d,h] * nmask[b,m] ----
__global__ void oproj_kernel(const float* __restrict__ ow)
{
    __shared__ float snm[32];
    if (threadIdx.x < 32) snm[threadIdx.x] = g_nmask[threadIdx.x];
    __syncthreads();
    int idx4 = blockIdx.x*256 + threadIdx.x;    // B*D*H/4 = 32768
    int h4 = (idx4 & 255) << 2;
    int dd = (idx4 >> 8) & 63;
    int b  = idx4 >> 14;
    float4 acc = make_float4(0.f, 0.f, 0.f, 0.f);
    #pragma unroll
    for (int mm = 0; mm < MN; mm++) {
        float4 v = *(const float4*)(ow + ((size_t)mm*DN + dd)*HN + h4);
        float wm = snm[b*16 + mm];
        acc.x = fmaf(v.x, wm, acc.x);
        acc.y = fmaf(v.y, wm, acc.y);
        acc.z = fmaf(v.z, wm, acc.z);
        acc.w = fmaf(v.w, wm, acc.w);
    }
    *(float4*)(g_oproj + (size_t)idx4*4) = acc;
}

// ---- final[b,t,h] = combined[b] @ oproj[b] ----
__global__ void final_kernel(float* __restrict__ out)
{
    int ht = blockIdx.x, qt = blockIdx.y, b = blockIdx.z;
    gemm64(g_comb  + (size_t)b*TN*DN + (size_t)qt*64*DN, DN,
           g_oproj + (size_t)b*DN*HN + ht*64,            HN,
           out     + (size_t)b*TN*HN + (size_t)qt*64*HN + ht*64, HN, DN);
}

extern "C" void kernel_launch(void* const* d_in, const int* in_sizes, int n_in,
                              void* d_out, int out_size)
{
    const float* hs    = (const float*)d_in[0];
    const float* wq    = (const float*)d_in[1];
    const float* wk    = (const float*)d_in[2];
    const float* wv    = (const float*)d_in[3];
    const float* ow    = (const float*)d_in[4];
    const float* gates = (const float*)d_in[5];
    float* out = (float*)d_out;

    const int attn_smem = (3*64*68 + 64*64 + 16) * 4;   // 68672 B
    cudaFuncSetAttribute(attn_kernel, cudaFuncAttributeMaxDynamicSharedMemorySize, attn_smem);

    init_kernel<<<1, 32>>>();
    proj_kernel<<<dim3(32, 16, 6), 256>>>(hs, wq, wk, wv);
    attn_kernel<<<dim3(32, 16, 2), 256, attn_smem>>>(out + OFF_SHA);
    gate_kernel<<<1, 32>>>(gates, out);
    combine_kernel<<<256, 256>>>(out + OFF_SHA);
    oproj_kernel<<<128, 256>>>(ow);
    final_kernel<<<dim3(16, 32, 2), 256>>>(out);
}

// round 3
// speedup vs baseline: 1.0309x; 1.0011x over previous
#include <cuda_runtime.h>
#include <math.h>

#define BN 2
#define TN 2048
#define HN 1024
#define DN 64
#define MN 16

#define QKV_ELEMS (BN*MN*TN*DN)

typedef unsigned long long u64;

// ---- packed f32x2 helpers (Blackwell 2x-rate fp32 path) ----
__device__ __forceinline__ u64 pk2(float lo, float hi) {
    u64 r; asm("mov.b64 %0, {%1,%2};" : "=l"(r) : "f"(lo), "f"(hi)); return r;
}
__device__ __forceinline__ void upk2(float& lo, float& hi, u64 v) {
    asm("mov.b64 {%0,%1}, %2;" : "=f"(lo), "=f"(hi) : "l"(v));
}
__device__ __forceinline__ void ffma2(u64& d, u64 a, u64 b) {
    asm("fma.rn.f32x2 %0, %1, %2, %0;" : "+l"(d) : "l"(a), "l"(b));
}
__device__ __forceinline__ void fmul2(u64& d, u64 a) {
    asm("mul.rn.f32x2 %0, %0, %1;" : "+l"(d) : "l"(a));
}

// ---- scratch (static device arrays; no allocation) ----
__device__ float  g_q[QKV_ELEMS];
__device__ float  g_k[QKV_ELEMS];
__device__ float  g_v[QKV_ELEMS];
__device__ double g_ent[BN*MN];
__device__ float  g_nmask[BN*MN];
__device__ float  g_comb[BN*TN*DN];
__device__ float  g_oproj[BN*DN*HN];

// ---- output layout (flattened tuple, f32) ----
#define OFF_SHA   (BN*TN*HN)                    // 4194304
#define OFF_LOGIT (OFF_SHA + BN*TN*MN*DN)       // 8388608
#define OFF_MASK  (OFF_LOGIT + BN*MN)           // 8388640
#define OFF_FBC   (OFF_MASK + BN*MN)            // 8388672

// ============================================================
// Generic 64x64 output-tile GEMM: C[64,64] = A[64,K] @ W[K,64]
// 256 threads, 4x4 micro-tile per thread, packed f32x2 FMAs.
// ============================================================
__device__ __forceinline__ void gemm64(const float* __restrict__ A, int lda,
                                       const float* __restrict__ W, int ldw,
                                       float* __restrict__ C, int ldc, int K)
{
    __shared__ float smem[16*68 + 16*64];
    float* sAt = smem;            // [k][row], stride 68
    float* sB  = smem + 16*68;    // [k][col], stride 64

    int tid = threadIdx.x;
    int r0 = (tid >> 4) << 2;
    int c0 = (tid & 15) << 2;
    int arow = tid >> 2;          // 0..63
    int ak   = (tid & 3) << 2;    // 0,4,8,12
    int wkr  = tid >> 4;          // 0..15
    int wn   = (tid & 15) << 2;   // 0..60

    u64 acc2[4][2] = {};
    for (int k0 = 0; k0 < K; k0 += 16) {
        __syncthreads();
        float4 av = *(const float4*)(A + (size_t)arow*lda + k0 + ak);
        sAt[(ak+0)*68 + arow] = av.x;
        sAt[(ak+1)*68 + arow] = av.y;
        sAt[(ak+2)*68 + arow] = av.z;
        sAt[(ak+3)*68 + arow] = av.w;
        *(float4*)(sB + wkr*64 + wn) = *(const float4*)(W + (size_t)(k0+wkr)*ldw + wn);
        __syncthreads();
        #pragma unroll
        for (int kk = 0; kk < 16; kk++) {
            float4 a4 = *(const float4*)(sAt + kk*68 + r0);
            ulonglong2 bu = *(const ulonglong2*)(sB + kk*64 + c0);
            u64 a0 = pk2(a4.x, a4.x), a1 = pk2(a4.y, a4.y);
            u64 a2 = pk2(a4.z, a4.z), a3 = pk2(a4.w, a4.w);
            ffma2(acc2[0][0], a0, bu.x); ffma2(acc2[0][1], a0, bu.y);
            ffma2(acc2[1][0], a1, bu.x); ffma2(acc2[1][1], a1, bu.y);
            ffma2(acc2[2][0], a2, bu.x); ffma2(acc2[2][1], a2, bu.y);
            ffma2(acc2[3][0], a3, bu.x); ffma2(acc2[3][1], a3, bu.y);
        }
    }
    #pragma unroll
    for (int i = 0; i < 4; i++) {
        float4 o;
        upk2(o.x, o.y, acc2[i][0]);
        upk2(o.z, o.w, acc2[i][1]);
        *(float4*)(C + (size_t)(r0+i)*ldc + c0) = o;
    }
}

// ---- QKV projections: q/k/v[b,m,t,d] = hidden[b,t,:] @ w[m,:,d] ----
__global__ void proj_kernel(const float* __restrict__ hs,
                            const float* __restrict__ wq,
                            const float* __restrict__ wk,
                            const float* __restrict__ wv)
{
    int qt = blockIdx.x;              // T tile (32)
    int m  = blockIdx.y;              // expert (16)
    int b  = blockIdx.z / 3;
    int which = blockIdx.z % 3;
    const float* W = (which == 0 ? wq : which == 1 ? wk : wv) + (size_t)m*HN*DN;
    float* out = (which == 0 ? g_q : which == 1 ? g_k : g_v)
                 + ((size_t)(b*MN + m)*TN + (size_t)qt*64)*DN;
    const float* A = hs + (size_t)b*TN*HN + (size_t)qt*64*HN;
    gemm64(A, HN, W, DN, out, DN, HN);
}

// ---- init: zero entropy accumulators ----
__global__ void init_kernel() { g_ent[threadIdx.x] = 0.0; }

// ============================================================
// Flash attention per (b, m, q-tile of 64). Online softmax with
// fused entropy:  H_t = m + log(l) - t/l,  t = sum s*exp(s-m).
// Packed f32x2 FMAs in both GEMM loops.
// ============================================================
__global__ void attn_kernel(float* __restrict__ out_sha)
{
    extern __shared__ float sm[];
    float* sQt  = sm;                 // [64 k][64 row] stride 68
    float* sKt  = sQt + 64*68;
    float* sPt  = sKt + 64*68;        // P transposed: [c][r] stride 68
    float* sV   = sPt + 64*68;        // [c][d] stride 64
    float* sRed = sV  + 64*64;        // 16

    int tid = threadIdx.x;
    int qt = blockIdx.x, m = blockIdx.y, b = blockIdx.z;
    const float* Qg = g_q + ((size_t)(b*MN + m)*TN + (size_t)qt*64)*DN;
    const float* Kg = g_k + (size_t)(b*MN + m)*TN*DN;
    const float* Vg = g_v + (size_t)(b*MN + m)*TN*DN;

    int tr = tid >> 4, tc = tid & 15;
    int r0 = tr << 2, c0 = tc << 2;
    int lrow = tid >> 4;              // 0..15
    int ld4  = (tid & 15) << 2;       // 0..60

    // load Q transposed, pre-scaled by 1/sqrt(D)
    #pragma unroll
    for (int p = 0; p < 4; p++) {
        int row = lrow + p*16;
        float4 v = *(const float4*)(Qg + (size_t)row*DN + ld4);
        sQt[(ld4+0)*68 + row] = v.x * 0.125f;
        sQt[(ld4+1)*68 + row] = v.y * 0.125f;
        sQt[(ld4+2)*68 + row] = v.z * 0.125f;
        sQt[(ld4+3)*68 + row] = v.w * 0.125f;
    }

    u64 o2[4][2] = {};
    float mrow[4], lrw[4], trw[4];
    #pragma unroll
    for (int i = 0; i < 4; i++) { mrow[i] = -INFINITY; lrw[i] = 0.f; trw[i] = 0.f; }

    for (int kt = 0; kt < TN/64; kt++) {
        __syncthreads();   // previous iteration fully done with sKt/sV/sPt
        #pragma unroll
        for (int p = 0; p < 4; p++) {
            int row = lrow + p*16;
            float4 kv = *(const float4*)(Kg + (size_t)(kt*64 + row)*DN + ld4);
            sKt[(ld4+0)*68 + row] = kv.x;
            sKt[(ld4+1)*68 + row] = kv.y;
            sKt[(ld4+2)*68 + row] = kv.z;
            sKt[(ld4+3)*68 + row] = kv.w;
            float4 vv = *(const float4*)(Vg + (size_t)(kt*64 + row)*DN + ld4);
            *(float4*)(sV + row*64 + ld4) = vv;
        }
        __syncthreads();

        // S = Q K^T (already scaled) — packed f32x2
        u64 s2[4][2] = {};
        #pragma unroll 8
        for (int kk = 0; kk < 64; kk++) {
            float4 a4 = *(const float4*)(sQt + kk*68 + r0);
            ulonglong2 bu = *(const ulonglong2*)(sKt + kk*68 + c0);
            u64 a0 = pk2(a4.x, a4.x), a1 = pk2(a4.y, a4.y);
            u64 a2 = pk2(a4.z, a4.z), a3 = pk2(a4.w, a4.w);
            ffma2(s2[0][0], a0, bu.x); ffma2(s2[0][1], a0, bu.y);
            ffma2(s2[1][0], a1, bu.x); ffma2(s2[1][1], a1, bu.y);
            ffma2(s2[2][0], a2, bu.x); ffma2(s2[2][1], a2, bu.y);
            ffma2(s2[3][0], a3, bu.x); ffma2(s2[3][1], a3, bu.y);
        }
        float s[4][4];
        #pragma unroll
        for (int i = 0; i < 4; i++) {
            upk2(s[i][0], s[i][1], s2[i][0]);
            upk2(s[i][2], s[i][3], s2[i][1]);
        }

        // online softmax + entropy stats (rows owned by 16-lane groups)
        #pragma unroll
        for (int i = 0; i < 4; i++) {
            float mx = fmaxf(fmaxf(s[i][0], s[i][1]), fmaxf(s[i][2], s[i][3]));
            #pragma unroll
            for (int off = 8; off; off >>= 1)
                mx = fmaxf(mx, __shfl_xor_sync(0xffffffffu, mx, off));
            float mnew  = fmaxf(mrow[i], mx);
            float alpha = __expf(mrow[i] - mnew);
            float ps = 0.f, ts = 0.f;
            #pragma unroll
            for (int j = 0; j < 4; j++) {
                float p = __expf(s[i][j] - mnew);
                ps += p;
                ts += p * s[i][j];
                s[i][j] = p;
            }
            #pragma unroll
            for (int off = 8; off; off >>= 1) {
                ps += __shfl_xor_sync(0xffffffffu, ps, off);
                ts += __shfl_xor_sync(0xffffffffu, ts, off);
            }
            lrw[i] = lrw[i]*alpha + ps;
            trw[i] = trw[i]*alpha + ts;
            u64 al2 = pk2(alpha, alpha);
            fmul2(o2[i][0], al2);
            fmul2(o2[i][1], al2);
            mrow[i] = mnew;
        }

        // write P^T to smem
        #pragma unroll
        for (int j = 0; j < 4; j++) {
            float4 pv = make_float4(s[0][j], s[1][j], s[2][j], s[3][j]);
            *(float4*)(sPt + (c0+j)*68 + r0) = pv;
        }
        __syncthreads();

        // O += P V — packed f32x2
        #pragma unroll 8
        for (int c = 0; c < 64; c++) {
            float4 a4 = *(const float4*)(sPt + c*68 + r0);
            ulonglong2 bu = *(const ulonglong2*)(sV + c*64 + c0);
            u64 a0 = pk2(a4.x, a4.x), a1 = pk2(a4.y, a4.y);
            u64 a2 = pk2(a4.z, a4.z), a3 = pk2(a4.w, a4.w);
            ffma2(o2[0][0], a0, bu.x); ffma2(o2[0][1], a0, bu.y);
            ffma2(o2[1][0], a1, bu.x); ffma2(o2[1][1], a1, bu.y);
            ffma2(o2[2][0], a2, bu.x); ffma2(o2[2][1], a2, bu.y);
            ffma2(o2[3][0], a3, bu.x); ffma2(o2[3][1], a3, bu.y);
        }
    }

    // epilogue: normalize + write sha in [B,T,M,D] layout
    #pragma unroll
    for (int i = 0; i < 4; i++) {
        float inv = 1.f / lrw[i];
        float4 ov;
        upk2(ov.x, ov.y, o2[i][0]);
        upk2(ov.z, ov.w, o2[i][1]);
        ov.x *= inv; ov.y *= inv; ov.z *= inv; ov.w *= inv;
        size_t t = (size_t)qt*64 + r0 + i;
        *(float4*)(out_sha + (((size_t)b*TN + t)*MN + m)*DN + c0) = ov;
    }

    // entropy sum for this 64-row tile
    if (tc == 0) {
        float e = 0.f;
        #pragma unroll
        for (int i = 0; i < 4; i++)
            e += mrow[i] + logf(lrw[i]) - trw[i]/lrw[i];
        sRed[tr] = e;
    }
    __syncthreads();
    if (tid == 0) {
        float ssum = 0.f;
        #pragma unroll
        for (int k = 0; k < 16; k++) ssum += sRed[k];
        atomicAdd(&g_ent[b*MN + m], (double)ssum);
    }
}

// ---- gating: affinity -> normalize -> STE mask -> fallback top-2 ----
__global__ void gate_kernel(const float* __restrict__ gates, float* __restrict__ out)
{
    __shared__ int cnt;
    int tid = threadIdx.x;            // 0..31 : b = tid/16, m = tid%16
    if (tid == 0) cnt = 0;
    __syncthreads();
    int m = tid & 15;

    float aff = -(float)(g_ent[tid] * (1.0 / (double)TN));

    float s = aff;
    #pragma unroll
    for (int off = 8; off; off >>= 1) s += __shfl_xor_sync(0xffffffffu, s, off);
    float mu = s * (1.f/16.f);
    float d = aff - mu;
    float v = d*d;
    #pragma unroll
    for (int off = 8; off; off >>= 1) v += __shfl_xor_sync(0xffffffffu, v, off);
    float sd = sqrtf(v * (1.f/15.f));               // ddof=1
    float norm = d / (sd + 1e-9f);

    float g = gates[m];
    float logit = norm - 1.f/(1.f + expf(-g));
    float hard = (logit > 0.f) ? 1.f : 0.f;

    float nact = hard;
    #pragma unroll
    for (int off = 8; off; off >>= 1) nact += __shfl_xor_sync(0xffffffffu, nact, off);
    bool inactive = (nact == 0.f);

    // top-2 by normalized affinity (butterfly argmax, tie -> lower index)
    float v1 = norm; int i1 = m;
    #pragma unroll
    for (int off = 8; off; off >>= 1) {
        float ov = __shfl_xor_sync(0xffffffffu, v1, off);
        int   oi = __shfl_xor_sync(0xffffffffu, i1, off);
        if (ov > v1 || (ov == v1 && oi < i1)) { v1 = ov; i1 = oi; }
    }
    float v2 = (m == i1) ? -INFINITY : norm; int i2 = m;
    #pragma unroll
    for (int off = 8; off; off >>= 1) {
        float ov = __shfl_xor_sync(0xffffffffu, v2, off);
        int   oi = __shfl_xor_sync(0xffffffffu, i2, off);
        if (ov > v2 || (ov == v2 && oi < i2)) { v2 = ov; i2 = oi; }
    }

    float mask = hard;
    if (inactive && (m == i1 || m == i2)) mask = 1.f;

    float na = mask;
    #pragma unroll
    for (int off = 8; off; off >>= 1) na += __shfl_xor_sync(0xffffffffu, na, off);
    float nm = mask / fmaxf(na, 1.f);

    out[OFF_LOGIT + tid] = logit;
    out[OFF_MASK  + tid] = mask;
    g_nmask[tid] = nm;

    if (m == 0 && inactive) atomicAdd(&cnt, 1);
    __syncthreads();
    if (tid == 0) out[OFF_FBC] = (float)cnt;
}

// ---- combined_heads[b,t,d] = sum_m sha[b,t,m,d] * nmask[b,m] ----
__global__ void combine_kernel(const float* __restrict__ sha)
{
    __shared__ float snm[32];
    if (threadIdx.x < 32) snm[threadIdx.x] = g_nmask[threadIdx.x];
    __syncthreads();
    int idx4 = blockIdx.x*256 + threadIdx.x;    // B*T*D/4 = 65536
    int d4 = (idx4 & 15) << 2;
    int t  = (idx4 >> 4) & (TN - 1);
    int b  = idx4 >> 15;
    const float* base = sha + ((size_t)(b*TN + t)*MN)*DN + d4;
    const float* w = snm + b*16;
    float4 acc = make_float4(0.f, 0.f, 0.f, 0.f);
    #pragma unroll
    for (int mm = 0; mm < MN; mm++) {
        float4 v = *(const float4*)(base + mm*DN);
        float wm = w[mm];
        acc.x = fmaf(v.x, wm, acc.x);
        acc.y = fmaf(v.y, wm, acc.y);
        acc.z = fmaf(v.z, wm, acc.z);
        acc.w = fmaf(v.w, wm, acc.w);
    }
    *(float4*)(g_comb + (size_t)idx4*4) = acc;
}

// ---- dynamic_o_proj[b,d,h] = sum_m o_weights[m,d,h] * nmask[b,m] ----
__global__ void oproj_kernel(const float* __restrict__ ow)
{
    __shared__ float snm[32];
    if (threadIdx.x < 32) snm[threadIdx.x] = g_nmask[threadIdx.x];
    __syncthreads();
    int idx4 = blockIdx.x*256 + threadIdx.x;    // B*D*H/4 = 32768
    int h4 = (idx4 & 255) << 2;
    int dd = (idx4 >> 8) & 63;
    int b  = idx4 >> 14;
    float4 acc = make_float4(0.f, 0.f, 0.f, 0.f);
    #pragma unroll
    for (int mm = 0; mm < MN; mm++) {
        float4 v = *(const float4*)(ow + ((size_t)mm*DN + dd)*HN + h4);
        float wm = snm[b*16 + mm];
        acc.x = fmaf(v.x, wm, acc.x);
        acc.y = fmaf(v.y, wm, acc.y);
        acc.z = fmaf(v.z, wm, acc.z);
        acc.w = fmaf(v.w, wm, acc.w);
    }
    *(float4*)(g_oproj + (size_t)idx4*4) = acc;
}

// ---- final[b,t,h] = combined[b] @ oproj[b] ----
__global__ void final_kernel(float* __restrict__ out)
{
    int ht = blockIdx.x, qt = blockIdx.y, b = blockIdx.z;
    gemm64(g_comb  + (size_t)b*TN*DN + (size_t)qt*64*DN, DN,
           g_oproj + (size_t)b*DN*HN + ht*64,            HN,
           out     + (size_t)b*TN*HN + (size_t)qt*64*HN + ht*64, HN, DN);
}

extern "C" void kernel_launch(void* const* d_in, const int* in_sizes, int n_in,
                              void* d_out, int out_size)
{
    const float* hs    = (const float*)d_in[0];
    const float* wq    = (const float*)d_in[1];
    const float* wk    = (const float*)d_in[2];
    const float* wv    = (const float*)d_in[3];
    const float* ow    = (const float*)d_in[4];
    const float* gates = (const float*)d_in[5];
    float* out = (float*)d_out;

    const int attn_smem = (3*64*68 + 64*64 + 16) * 4;   // 68672 B
    cudaFuncSetAttribute(attn_kernel, cudaFuncAttributeMaxDynamicSharedMemorySize, attn_smem);

    init_kernel<<<1, 32>>>();
    proj_kernel<<<dim3(32, 16, 6), 256>>>(hs, wq, wk, wv);
    attn_kernel<<<dim3(32, 16, 2), 256, attn_smem>>>(out + OFF_SHA);
    gate_kernel<<<1, 32>>>(gates, out);
    combine_kernel<<<256, 256>>>(out + OFF_SHA);
    oproj_kernel<<<128, 256>>>(ow);
    final_kernel<<<dim3(16, 32, 2), 256>>>(out);
}